// round 2
// baseline (speedup 1.0000x reference)
#include <cuda_runtime.h>
#include <math.h>

// ---------------------------------------------------------------------------
// TransNetSweeping on GB300 — fused fp32 implementation.
//
// Math: A_l = [[I, aW],[-aW^T, cI]], a=0.1, c=11.
//   Solve A_l [u;v] = [p;q]:
//     S = I + (a^2/c) W W^T,  M = S^{-1},  N = (a/c) M W
//     u = M p - N q
//     v = (q + a W^T u)/c
//   p = a*b_l + carry_u ; q = 10*tanh(z_l_u) + carry_v
//
// Sweep runs a FIXED 15 iterations (reference stops early only when already
// converged below 1e-4 — extra iterations differ by <<1e-3 on softmax).
// Every batch row is independent -> one persistent kernel, state in smem.
// ---------------------------------------------------------------------------

#define BATCH    2048
#define U        128
#define NLAYERS  8
#define NSTEPS   15

#define DT_A     0.1f          // a = DT
#define CVAL     11.0f         // c = 1 + DT/EPS
#define INVC     (1.0f/11.0f)
#define TANHK    10.0f         // DT/EPS

// scratch (device globals — no allocation allowed)
__device__ float g_zin[BATCH * 256];                 // 2 MB
__device__ float g_Mt [NLAYERS * U * U];             // Mt[l][k][j] = M[j][k]
__device__ float g_Nt [NLAYERS * U * U];             // Nt[l][k][j] = N[j][k]
__device__ float g_WT [U * U];                       // layer 7: WT[i][k] = W[k][i]

__device__ __forceinline__ float4 ld4(const float* p) { return *(const float4*)p; }
__device__ __forceinline__ void   st4(float* p, float4 v) { *(float4*)p = v; }

// ---------------------------------------------------------------------------
// Kernel 1: input projection  z_in = [x1, tanh(x1)], x1 = x @ w_in^T + b_in
// grid 128, block 128; CTA = 16 rows x 128 cols; K=784 in 49 chunks of 16.
// ---------------------------------------------------------------------------
__global__ __launch_bounds__(128) void k_input(const float* __restrict__ x,
                                               const float* __restrict__ win,
                                               const float* __restrict__ bin)
{
    __shared__ float ws[16 * 132];   // ws[kk][n], padded row 132
    __shared__ float xs[16 * 20];    // xs[kk][r], padded row 20

    const int tid = threadIdx.x;
    const int rg  = tid >> 5;        // 0..3  (4 rows each)
    const int cg  = tid & 31;        // 0..31 (4 cols each)
    const int row0 = blockIdx.x * 16;

    float4 acc[4];
#pragma unroll
    for (int r = 0; r < 4; r++) acc[r] = make_float4(0.f, 0.f, 0.f, 0.f);

    for (int kc = 0; kc < 49; kc++) {
        const int k0 = kc * 16;
        __syncthreads();
        {   // stage w_in[n][k0..k0+15] transposed -> ws[kk][n], n = tid
            const float* wr = win + tid * 784 + k0;
            float4 a = ld4(wr), b = ld4(wr + 4), c = ld4(wr + 8), d = ld4(wr + 12);
            ws[ 0*132 + tid] = a.x; ws[ 1*132 + tid] = a.y;
            ws[ 2*132 + tid] = a.z; ws[ 3*132 + tid] = a.w;
            ws[ 4*132 + tid] = b.x; ws[ 5*132 + tid] = b.y;
            ws[ 6*132 + tid] = b.z; ws[ 7*132 + tid] = b.w;
            ws[ 8*132 + tid] = c.x; ws[ 9*132 + tid] = c.y;
            ws[10*132 + tid] = c.z; ws[11*132 + tid] = c.w;
            ws[12*132 + tid] = d.x; ws[13*132 + tid] = d.y;
            ws[14*132 + tid] = d.z; ws[15*132 + tid] = d.w;
        }
        {   // stage x[r][k0..k0+15] transposed -> xs[kk][r]
            const int r  = tid >> 3;          // 0..15
            const int kp = tid & 7;           // 0..7  (pairs)
            const float2 v = *(const float2*)(x + (row0 + r) * 784 + k0 + kp * 2);
            xs[(kp*2 + 0) * 20 + r] = v.x;
            xs[(kp*2 + 1) * 20 + r] = v.y;
        }
        __syncthreads();
#pragma unroll
        for (int kk = 0; kk < 16; kk++) {
            float4 wv = ld4(&ws[kk * 132 + cg * 4]);
#pragma unroll
            for (int rr = 0; rr < 4; rr++) {
                float xv = xs[kk * 20 + rg * 4 + rr];
                acc[rr].x += xv * wv.x; acc[rr].y += xv * wv.y;
                acc[rr].z += xv * wv.z; acc[rr].w += xv * wv.w;
            }
        }
    }

    const float4 b4 = ld4(bin + cg * 4);
#pragma unroll
    for (int rr = 0; rr < 4; rr++) {
        const int row = row0 + rg * 4 + rr;
        float4 v;
        v.x = acc[rr].x + b4.x; v.y = acc[rr].y + b4.y;
        v.z = acc[rr].z + b4.z; v.w = acc[rr].w + b4.w;
        st4(&g_zin[row * 256 + cg * 4], v);
        float4 t;
        t.x = tanhf(v.x); t.y = tanhf(v.y); t.z = tanhf(v.z); t.w = tanhf(v.w);
        st4(&g_zin[row * 256 + 128 + cg * 4], t);
    }
}

// ---------------------------------------------------------------------------
// Kernel 2: per-layer precompute: M = (I + (a^2/c) W W^T)^{-1}, N = (a/c) M W.
// grid 8 (one CTA per layer), block 256, dynamic smem ~195 KB.
// S is I + tiny PSD -> Gauss-Jordan without pivoting is safe.
// ---------------------------------------------------------------------------
#define WS_S 129    // Wsh row stride (bank-conflict pad)
#define AS_S 260    // aug row stride (float4-aligned pad)
#define PREP_SMEM ((128*WS_S + 128*AS_S + 128) * 4)

__global__ __launch_bounds__(256) void k_prep(const float* __restrict__ wblocks)
{
    extern __shared__ float sm[];
    float* Wsh  = sm;                        // [128][129]
    float* aug  = sm + 128 * WS_S;           // [128][260] (left S->MT, right I->M)
    float* colb = aug + 128 * AS_S;          // [128] pivot column snapshot

    const int tid = threadIdx.x;
    const int l   = blockIdx.x;
    const float* Wg = wblocks + l * U * U;

    // load W
    for (int idx = tid; idx < U * U; idx += 256)
        Wsh[(idx >> 7) * WS_S + (idx & 127)] = Wg[idx];
    __syncthreads();

    // S = I + (a^2/c) W W^T  into aug left; I into aug right
    const float kscl = (DT_A * DT_A) * INVC;
#pragma unroll 1
    for (int rep = 0; rep < 2; rep++) {
        const int pos = tid + rep * 256;     // 512 tiles of 4x8
        const int ti = pos >> 4;             // 0..31
        const int tj = pos & 15;             // 0..15
        float acc[4][8];
#pragma unroll
        for (int r = 0; r < 4; r++)
#pragma unroll
            for (int cjj = 0; cjj < 8; cjj++) acc[r][cjj] = 0.f;
        for (int k = 0; k < U; k++) {
            float wi[4], wj[8];
#pragma unroll
            for (int r = 0; r < 4; r++)   wi[r]   = Wsh[(ti*4 + r)   * WS_S + k];
#pragma unroll
            for (int cjj = 0; cjj < 8; cjj++) wj[cjj] = Wsh[(tj*8 + cjj) * WS_S + k];
#pragma unroll
            for (int r = 0; r < 4; r++)
#pragma unroll
                for (int cjj = 0; cjj < 8; cjj++) acc[r][cjj] += wi[r] * wj[cjj];
        }
#pragma unroll
        for (int r = 0; r < 4; r++)
#pragma unroll
            for (int cjj = 0; cjj < 8; cjj++) {
                int i = ti*4 + r, j = tj*8 + cjj;
                aug[i * AS_S + j] = kscl * acc[r][cjj] + (i == j ? 1.f : 0.f);
            }
    }
    for (int idx = tid; idx < U * U; idx += 256) {
        int i = idx >> 7, j = idx & 127;
        aug[i * AS_S + 128 + j] = (i == j) ? 1.f : 0.f;
    }

    // Gauss-Jordan (no pivoting)
    const int f4c = tid & 63;    // float4 column 0..63 (256 cols)
    const int rgp = tid >> 6;    // row group 0..3 (32 rows each)
    for (int p = 0; p < U; p++) {
        __syncthreads();
        const float inv = 1.0f / aug[p * AS_S + p];
        if (tid < 128 && tid != p) colb[tid] = aug[tid * AS_S + p];
        __syncthreads();
        aug[p * AS_S + tid] *= inv;
        __syncthreads();
        const float4 rp = ld4(&aug[p * AS_S + f4c * 4]);
        for (int i = rgp * 32; i < rgp * 32 + 32; i++) {
            if (i == p) continue;
            const float fac = colb[i];
            float4 a = ld4(&aug[i * AS_S + f4c * 4]);
            a.x -= fac * rp.x; a.y -= fac * rp.y;
            a.z -= fac * rp.z; a.w -= fac * rp.w;
            st4(&aug[i * AS_S + f4c * 4], a);
        }
    }
    __syncthreads();

    // transpose: aug_left[m][j] := M[j][m]  (reads right half only)
    for (int idx = tid; idx < U * U; idx += 256) {
        int m = idx >> 7, j = idx & 127;
        aug[m * AS_S + j] = aug[j * AS_S + 128 + m];
    }
    __syncthreads();

    // Mt[l][k][j] = M[j][k] = aug_left[k][j]
    for (int idx = tid; idx < U * U; idx += 256) {
        int k = idx >> 7, j = idx & 127;
        g_Mt[l * U * U + idx] = aug[k * AS_S + j];
    }

    // Nt[l][k][j] = (a/c) * sum_m M[j][m] W[m][k] = (a/c) sum_m aug_left[m][j]*Wsh[m][k]
    const float ac = DT_A * INVC;
#pragma unroll 1
    for (int rep = 0; rep < 2; rep++) {
        const int pos = tid + rep * 256;
        const int tk = pos >> 4;   // 0..31 (4 k's)
        const int tj = pos & 15;   // 0..15 (8 j's)
        float acc[4][8];
#pragma unroll
        for (int r = 0; r < 4; r++)
#pragma unroll
            for (int cjj = 0; cjj < 8; cjj++) acc[r][cjj] = 0.f;
        for (int m = 0; m < U; m++) {
            float wv[4], mv[8];
#pragma unroll
            for (int r = 0; r < 4; r++)   wv[r]   = Wsh[m * WS_S + tk*4 + r];
#pragma unroll
            for (int cjj = 0; cjj < 8; cjj++) mv[cjj] = aug[m * AS_S + tj*8 + cjj];
#pragma unroll
            for (int r = 0; r < 4; r++)
#pragma unroll
                for (int cjj = 0; cjj < 8; cjj++) acc[r][cjj] += wv[r] * mv[cjj];
        }
#pragma unroll
        for (int r = 0; r < 4; r++)
#pragma unroll
            for (int cjj = 0; cjj < 8; cjj++)
                g_Nt[l * U * U + (tk*4 + r) * U + tj*8 + cjj] = ac * acc[r][cjj];
    }

    // WT for layer 7: WT[i][j] = W[j][i]
    if (l == NLAYERS - 1) {
        for (int idx = tid; idx < U * U; idx += 256) {
            int i = idx >> 7, j = idx & 127;
            g_WT[i * U + j] = Wsh[j * WS_S + i];
        }
    }
}

// ---------------------------------------------------------------------------
// Kernel 3: fused sweep (15 x 8 layer-steps) + final block + logits + softmax.
// grid 128, block 128 (4 warps); CTA owns 16 rows; all z-state in smem.
// Thread tile 4 rows x 4 cols; weights staged from L2 in 32-row chunks.
// ---------------------------------------------------------------------------
// smem float offsets
#define SW_ZIN 0                 // 16*256
#define SW_ZLS (SW_ZIN + 4096)   // 8*16*256
#define SW_PS  (SW_ZLS + 32768)  // 16*128
#define SW_QS  (SW_PS  + 2048)   // 16*128
#define SW_WB0 (SW_QS  + 2048)   // 32*128
#define SW_WB1 (SW_WB0 + 4096)   // 32*128
#define SW_BB  (SW_WB1 + 4096)   // 8*128
#define SW_SCO (SW_BB  + 1024)   // 10*128 w_out + 160 logits
#define SWEEP_SMEM ((SW_SCO + 1280 + 160) * 4)

__global__ __launch_bounds__(128, 1) void k_sweep(const float* __restrict__ wblocks,
                                                  const float* __restrict__ bblocks,
                                                  const float* __restrict__ wout,
                                                  const float* __restrict__ bout,
                                                  float* __restrict__ out)
{
    extern __shared__ float sm[];
    float* zin = sm + SW_ZIN;
    float* zlsb = sm + SW_ZLS;
    float* ps  = sm + SW_PS;
    float* qs  = sm + SW_QS;
    float* wb0 = sm + SW_WB0;
    float* wb1 = sm + SW_WB1;
    float* bb  = sm + SW_BB;
    float* sco = sm + SW_SCO;

    const int tid = threadIdx.x;
    const int rg  = tid >> 5;    // warp id = row group (4 rows)
    const int cg  = tid & 31;    // 4 cols
    const int row0 = blockIdx.x * 16;

    // load z_in, b_blocks; init z_ls
    for (int idx = tid; idx < 4096; idx += 128) zin[idx] = g_zin[row0 * 256 + idx];
    for (int idx = tid; idx < 1024; idx += 128) bb[idx] = bblocks[idx];
    __syncthreads();
    for (int idx = tid; idx < 32768; idx += 128) zlsb[idx] = zin[idx & 4095];
    __syncthreads();

    for (int it = 0; it < NSTEPS; it++) {
        for (int l = 0; l < NLAYERS; l++) {
            const float* carry = (l == 0) ? zin : (zlsb + (l - 1) * 4096);
            float* zl = zlsb + l * 4096;

            // stage p, q
            for (int idx = tid; idx < 2048; idx += 128) {
                const int r = idx >> 7, k = idx & 127;
                ps[idx] = DT_A * bb[l * U + k] + carry[r * 256 + k];
                qs[idx] = TANHK * tanhf(zl[r * 256 + k]) + carry[r * 256 + 128 + k];
            }
            __syncthreads();

            // ---- u = M p - N q ----
            float4 acc[4];
#pragma unroll
            for (int r = 0; r < 4; r++) acc[r] = make_float4(0.f, 0.f, 0.f, 0.f);
            const float* Mt = g_Mt + l * U * U;
            const float* Nt = g_Nt + l * U * U;
            for (int kc4 = 0; kc4 < 4; kc4++) {
                __syncthreads();
                {
                    const float4* m4 = (const float4*)(Mt + kc4 * 4096);
                    const float4* n4 = (const float4*)(Nt + kc4 * 4096);
                    float4* w0 = (float4*)wb0;
                    float4* w1 = (float4*)wb1;
#pragma unroll
                    for (int t = 0; t < 8; t++) {
                        w0[tid + t * 128] = m4[tid + t * 128];
                        w1[tid + t * 128] = n4[tid + t * 128];
                    }
                }
                __syncthreads();
#pragma unroll 4
                for (int kk = 0; kk < 32; kk++) {
                    const int k = kc4 * 32 + kk;
                    const float4 m = ld4(&wb0[kk * 128 + cg * 4]);
                    const float4 n = ld4(&wb1[kk * 128 + cg * 4]);
#pragma unroll
                    for (int rr = 0; rr < 4; rr++) {
                        const float pv = ps[(rg * 4 + rr) * 128 + k];
                        const float qv = qs[(rg * 4 + rr) * 128 + k];
                        acc[rr].x += pv * m.x - qv * n.x;
                        acc[rr].y += pv * m.y - qv * n.y;
                        acc[rr].z += pv * m.z - qv * n.z;
                        acc[rr].w += pv * m.w - qv * n.w;
                    }
                }
            }
            __syncthreads();
#pragma unroll
            for (int rr = 0; rr < 4; rr++)
                st4(&zl[(rg * 4 + rr) * 256 + cg * 4], acc[rr]);
            __syncthreads();

            // ---- v = (q + a * W^T u)/c ----
            float4 vac[4];
#pragma unroll
            for (int r = 0; r < 4; r++) vac[r] = make_float4(0.f, 0.f, 0.f, 0.f);
            const float* Wl = wblocks + l * U * U;
            for (int jc = 0; jc < 4; jc++) {
                __syncthreads();
                {
                    const float4* w4 = (const float4*)(Wl + jc * 4096);
                    float4* w0 = (float4*)wb0;
#pragma unroll
                    for (int t = 0; t < 8; t++) w0[tid + t * 128] = w4[tid + t * 128];
                }
                __syncthreads();
#pragma unroll 4
                for (int jj = 0; jj < 32; jj++) {
                    const int j = jc * 32 + jj;
                    const float4 w = ld4(&wb0[jj * 128 + cg * 4]);
#pragma unroll
                    for (int rr = 0; rr < 4; rr++) {
                        const float uv = zl[(rg * 4 + rr) * 256 + j];
                        vac[rr].x += uv * w.x; vac[rr].y += uv * w.y;
                        vac[rr].z += uv * w.z; vac[rr].w += uv * w.w;
                    }
                }
            }
#pragma unroll
            for (int rr = 0; rr < 4; rr++) {
                const float4 q4 = ld4(&qs[(rg * 4 + rr) * 128 + cg * 4]);
                float4 v;
                v.x = (q4.x + DT_A * vac[rr].x) * INVC;
                v.y = (q4.y + DT_A * vac[rr].y) * INVC;
                v.z = (q4.z + DT_A * vac[rr].z) * INVC;
                v.w = (q4.w + DT_A * vac[rr].w) * INVC;
                st4(&zl[(rg * 4 + rr) * 256 + 128 + cg * 4], v);
            }
            __syncthreads();
        }
    }

    // ---- final block: u_out = z_in_u + a*b7 - a*(v7 @ W7^T), into ps ----
    {
        float4 uac[4];
#pragma unroll
        for (int r = 0; r < 4; r++) uac[r] = make_float4(0.f, 0.f, 0.f, 0.f);
        const float* zl7 = zlsb + 7 * 4096;
        for (int ic = 0; ic < 4; ic++) {
            __syncthreads();
            {
                const float4* w4 = (const float4*)(g_WT + ic * 4096);
                float4* w0 = (float4*)wb0;
#pragma unroll
                for (int t = 0; t < 8; t++) w0[tid + t * 128] = w4[tid + t * 128];
            }
            __syncthreads();
#pragma unroll 4
            for (int ii = 0; ii < 32; ii++) {
                const int i = ic * 32 + ii;
                const float4 w = ld4(&wb0[ii * 128 + cg * 4]);   // WT[i][k-range]
#pragma unroll
                for (int rr = 0; rr < 4; rr++) {
                    const float vv = zl7[(rg * 4 + rr) * 256 + 128 + i];
                    uac[rr].x += vv * w.x; uac[rr].y += vv * w.y;
                    uac[rr].z += vv * w.z; uac[rr].w += vv * w.w;
                }
            }
        }
        __syncthreads();
#pragma unroll
        for (int rr = 0; rr < 4; rr++) {
            const float4 z4 = ld4(&zin[(rg * 4 + rr) * 256 + cg * 4]);
            const float4 b4 = ld4(&bb[7 * U + cg * 4]);
            float4 uo;
            uo.x = z4.x + DT_A * b4.x - DT_A * uac[rr].x;
            uo.y = z4.y + DT_A * b4.y - DT_A * uac[rr].y;
            uo.z = z4.z + DT_A * b4.z - DT_A * uac[rr].z;
            uo.w = z4.w + DT_A * b4.w - DT_A * uac[rr].w;
            st4(&ps[(rg * 4 + rr) * 128 + cg * 4], uo);
        }
    }
    __syncthreads();

    // ---- logits + softmax ----
    for (int idx = tid; idx < 1280; idx += 128) sco[idx] = wout[idx];
    __syncthreads();
    float* lg = sco + 1280;
    for (int t = tid; t < 160; t += 128) {
        const int r = t / 10, o = t % 10;
        float a = bout[o];
        for (int k = 0; k < U; k++) a += ps[r * 128 + k] * sco[o * 128 + k];
        lg[t] = a;
    }
    __syncthreads();
    if (tid < 16) {
        float mx = -1e30f;
#pragma unroll
        for (int o = 0; o < 10; o++) mx = fmaxf(mx, lg[tid * 10 + o]);
        float e[10], s = 0.f;
#pragma unroll
        for (int o = 0; o < 10; o++) { e[o] = expf(lg[tid * 10 + o] - mx); s += e[o]; }
        const float inv = 1.0f / s;
#pragma unroll
        for (int o = 0; o < 10; o++) out[(row0 + tid) * 10 + o] = e[o] * inv;
    }
}

// ---------------------------------------------------------------------------
extern "C" void kernel_launch(void* const* d_in, const int* in_sizes, int n_in,
                              void* d_out, int out_size)
{
    const float* x       = (const float*)d_in[0];
    const float* w_in    = (const float*)d_in[1];
    const float* b_in    = (const float*)d_in[2];
    const float* w_blk   = (const float*)d_in[3];
    const float* b_blk   = (const float*)d_in[4];
    const float* w_out   = (const float*)d_in[5];
    const float* b_out   = (const float*)d_in[6];
    float* out = (float*)d_out;

    cudaFuncSetAttribute(k_prep,  cudaFuncAttributeMaxDynamicSharedMemorySize, PREP_SMEM);
    cudaFuncSetAttribute(k_sweep, cudaFuncAttributeMaxDynamicSharedMemorySize, SWEEP_SMEM);

    k_input<<<128, 128>>>(x, w_in, b_in);
    k_prep <<<8,   256, PREP_SMEM>>>(w_blk);
    k_sweep<<<128, 128, SWEEP_SMEM>>>(w_blk, b_blk, w_out, b_out, out);
}

// round 3
// speedup vs baseline: 1.2050x; 1.2050x over previous
#include <cuda_runtime.h>
#include <cstdint>
#include <math.h>

// ---------------------------------------------------------------------------
// TransNetSweeping on GB300 — fused fp32, async-pipelined weights (R2).
//
// Math: A_l = [[I, aW],[-aW^T, cI]], a=0.1, c=11.
//   S = I + (a^2/c) W W^T,  M = S^{-1},  N = (a/c) M W
//   u = M p - N q ;  v = (q + a W^T u)/c
//   p = a*b_l + carry_u ; q = 10*tanh(z_l_u) + carry_v
// Fixed 15 Gauss-Seidel sweeps (matches reference to fp32 noise, verified R1).
//
// k_sweep: 128 CTAs x 128 thr. Warp owns 4 batch rows end-to-end (all state
// warp-local). Weights stream via cp.async.bulk double buffer (2x32KB slots),
// one flat 722-chunk sequence; only cross-warp sync = slot reuse.
// ---------------------------------------------------------------------------

#define BATCH    2048
#define U        128
#define NLAYERS  8
#define NSTEPS   15

#define DT_A     0.1f
#define INVC     (1.0f/11.0f)
#define TANHK    10.0f

#define NCHUNKS  (NSTEPS * NLAYERS * 6 + 2)   // 722

__device__ float g_zin[BATCH * 256];
__device__ float g_Mt [NLAYERS * U * U];      // Mt[l][k][j] = M[j][k]
__device__ float g_Nt [NLAYERS * U * U];      // Nt[l][k][j] = N[j][k]
__device__ float g_WT [U * U];                // WT[i][k] = W7[k][i]

__device__ __forceinline__ float4 ld4(const float* p) { return *(const float4*)p; }
__device__ __forceinline__ void   st4(float* p, float4 v) { *(float4*)p = v; }
#define FC(v,t) (((const float*)&(v))[t])

__device__ __forceinline__ uint32_t s2u(const void* p) {
    uint32_t a;
    asm("{ .reg .u64 t; cvta.to.shared.u64 t, %1; cvt.u32.u64 %0, t; }" : "=r"(a) : "l"(p));
    return a;
}
__device__ __forceinline__ void mbar_init(uint32_t m, uint32_t cnt) {
    asm volatile("mbarrier.init.shared.b64 [%0], %1;" :: "r"(m), "r"(cnt) : "memory");
}
__device__ __forceinline__ void mbar_expect(uint32_t m, uint32_t tx) {
    asm volatile("mbarrier.arrive.expect_tx.shared.b64 _, [%0], %1;" :: "r"(m), "r"(tx) : "memory");
}
__device__ __forceinline__ void bulk_g2s(uint32_t dst, const void* src, uint32_t bytes, uint32_t m) {
    asm volatile("cp.async.bulk.shared::cluster.global.mbarrier::complete_tx::bytes [%0], [%1], %2, [%3];"
                 :: "r"(dst), "l"(src), "r"(bytes), "r"(m) : "memory");
}
__device__ __forceinline__ void mbar_wait(uint32_t m, uint32_t phase) {
    uint32_t done;
    do {
        asm volatile("{\n\t.reg .pred p;\n\t"
                     "mbarrier.try_wait.parity.acquire.cta.shared::cta.b64 p, [%1], %2, 0x989680;\n\t"
                     "selp.b32 %0, 1, 0, p;\n\t}"
                     : "=r"(done) : "r"(m), "r"(phase) : "memory");
    } while (!done);
}

// ---------------------------------------------------------------------------
// k_pre: merged prep (CTAs 0..7) + input projection (CTAs 8..135). Block 256.
// ---------------------------------------------------------------------------
#define WS_S 129
#define AS_S 260
#define PREP_SMEM ((128*WS_S + 128*AS_S + 128) * 4)

__device__ void prep_body(float* sm, const float* __restrict__ wblocks, int l)
{
    float* Wsh  = sm;
    float* aug  = sm + 128 * WS_S;
    float* colb = aug + 128 * AS_S;
    const int tid = threadIdx.x;
    const float* Wg = wblocks + l * U * U;

    for (int idx = tid; idx < U * U; idx += 256)
        Wsh[(idx >> 7) * WS_S + (idx & 127)] = Wg[idx];
    __syncthreads();

    const float kscl = (DT_A * DT_A) * INVC;
#pragma unroll 1
    for (int rep = 0; rep < 2; rep++) {
        const int pos = tid + rep * 256;
        const int ti = pos >> 4, tj = pos & 15;
        float acc[4][8];
#pragma unroll
        for (int r = 0; r < 4; r++)
#pragma unroll
            for (int j = 0; j < 8; j++) acc[r][j] = 0.f;
        for (int k = 0; k < U; k++) {
            float wi[4], wj[8];
#pragma unroll
            for (int r = 0; r < 4; r++) wi[r] = Wsh[(ti*4 + r) * WS_S + k];
#pragma unroll
            for (int j = 0; j < 8; j++) wj[j] = Wsh[(tj*8 + j) * WS_S + k];
#pragma unroll
            for (int r = 0; r < 4; r++)
#pragma unroll
                for (int j = 0; j < 8; j++) acc[r][j] += wi[r] * wj[j];
        }
#pragma unroll
        for (int r = 0; r < 4; r++)
#pragma unroll
            for (int j = 0; j < 8; j++) {
                int i = ti*4 + r, jj = tj*8 + j;
                aug[i * AS_S + jj] = kscl * acc[r][j] + (i == jj ? 1.f : 0.f);
            }
    }
    for (int idx = tid; idx < U * U; idx += 256) {
        int i = idx >> 7, j = idx & 127;
        aug[i * AS_S + 128 + j] = (i == j) ? 1.f : 0.f;
    }

    const int f4c = tid & 63, rgp = tid >> 6;
    for (int p = 0; p < U; p++) {
        __syncthreads();
        const float inv = 1.0f / aug[p * AS_S + p];
        if (tid < 128 && tid != p) colb[tid] = aug[tid * AS_S + p];
        __syncthreads();
        aug[p * AS_S + tid] *= inv;
        __syncthreads();
        const float4 rp = ld4(&aug[p * AS_S + f4c * 4]);
        for (int i = rgp * 32; i < rgp * 32 + 32; i++) {
            if (i == p) continue;
            const float fac = colb[i];
            float4 a = ld4(&aug[i * AS_S + f4c * 4]);
            a.x -= fac * rp.x; a.y -= fac * rp.y;
            a.z -= fac * rp.z; a.w -= fac * rp.w;
            st4(&aug[i * AS_S + f4c * 4], a);
        }
    }
    __syncthreads();

    // aug_left[m][j] := M[j][m]
    for (int idx = tid; idx < U * U; idx += 256) {
        int m = idx >> 7, j = idx & 127;
        aug[m * AS_S + j] = aug[j * AS_S + 128 + m];
    }
    __syncthreads();

    for (int idx = tid; idx < U * U; idx += 256) {
        int k = idx >> 7, j = idx & 127;
        g_Mt[l * U * U + idx] = aug[k * AS_S + j];
    }

    const float ac = DT_A * INVC;
#pragma unroll 1
    for (int rep = 0; rep < 2; rep++) {
        const int pos = tid + rep * 256;
        const int tk = pos >> 4, tj = pos & 15;
        float acc[4][8];
#pragma unroll
        for (int r = 0; r < 4; r++)
#pragma unroll
            for (int j = 0; j < 8; j++) acc[r][j] = 0.f;
        for (int m = 0; m < U; m++) {
            float wv[4], mv[8];
#pragma unroll
            for (int r = 0; r < 4; r++) wv[r] = Wsh[m * WS_S + tk*4 + r];
#pragma unroll
            for (int j = 0; j < 8; j++) mv[j] = aug[m * AS_S + tj*8 + j];
#pragma unroll
            for (int r = 0; r < 4; r++)
#pragma unroll
                for (int j = 0; j < 8; j++) acc[r][j] += wv[r] * mv[j];
        }
#pragma unroll
        for (int r = 0; r < 4; r++)
#pragma unroll
            for (int j = 0; j < 8; j++)
                g_Nt[l * U * U + (tk*4 + r) * U + tj*8 + j] = ac * acc[r][j];
    }

    if (l == NLAYERS - 1) {
        for (int idx = tid; idx < U * U; idx += 256) {
            int i = idx >> 7, j = idx & 127;
            g_WT[i * U + j] = Wsh[j * WS_S + i];
        }
    }
}

__device__ void input_body(float* sm, const float* __restrict__ x,
                           const float* __restrict__ win,
                           const float* __restrict__ bin, int bid)
{
    float* ws = sm;            // [16][132]
    float* xs = sm + 16 * 132; // [16][20]
    const int tid = threadIdx.x;
    const int row0 = bid * 16;
    const int rg = tid >> 5, cg = tid & 31;   // valid for tid<128 compute

    float4 acc[4];
#pragma unroll
    for (int r = 0; r < 4; r++) acc[r] = make_float4(0.f, 0.f, 0.f, 0.f);

    for (int kc = 0; kc < 49; kc++) {
        const int k0 = kc * 16;
        __syncthreads();
        {   // ws[kk][n] = win[n][k0+kk]; 256 threads, 8 values each
            const int n = tid & 127, h = tid >> 7;
            const float* wr = win + n * 784 + k0 + h * 8;
            float4 a = ld4(wr), b = ld4(wr + 4);
            ws[(h*8+0)*132 + n] = a.x; ws[(h*8+1)*132 + n] = a.y;
            ws[(h*8+2)*132 + n] = a.z; ws[(h*8+3)*132 + n] = a.w;
            ws[(h*8+4)*132 + n] = b.x; ws[(h*8+5)*132 + n] = b.y;
            ws[(h*8+6)*132 + n] = b.z; ws[(h*8+7)*132 + n] = b.w;
        }
        {   // xs[kk][r] = x[row0+r][k0+kk]; 256 values, 1 each
            const int r = tid >> 4, kk = tid & 15;
            xs[kk * 20 + r] = x[(row0 + r) * 784 + k0 + kk];
        }
        __syncthreads();
        if (tid < 128) {
#pragma unroll
            for (int kk = 0; kk < 16; kk++) {
                float4 wv = ld4(&ws[kk * 132 + cg * 4]);
#pragma unroll
                for (int rr = 0; rr < 4; rr++) {
                    float xv = xs[kk * 20 + rg * 4 + rr];
                    acc[rr].x += xv * wv.x; acc[rr].y += xv * wv.y;
                    acc[rr].z += xv * wv.z; acc[rr].w += xv * wv.w;
                }
            }
        }
    }

    if (tid < 128) {
        const float4 b4 = ld4(bin + cg * 4);
#pragma unroll
        for (int rr = 0; rr < 4; rr++) {
            const int row = row0 + rg * 4 + rr;
            float4 v;
            v.x = acc[rr].x + b4.x; v.y = acc[rr].y + b4.y;
            v.z = acc[rr].z + b4.z; v.w = acc[rr].w + b4.w;
            st4(&g_zin[row * 256 + cg * 4], v);
            float4 t;
            t.x = tanhf(v.x); t.y = tanhf(v.y); t.z = tanhf(v.z); t.w = tanhf(v.w);
            st4(&g_zin[row * 256 + 128 + cg * 4], t);
        }
    }
}

__global__ __launch_bounds__(256) void k_pre(const float* __restrict__ x,
                                             const float* __restrict__ win,
                                             const float* __restrict__ bin,
                                             const float* __restrict__ wblocks)
{
    extern __shared__ float sm[];
    if (blockIdx.x < 8) prep_body(sm, wblocks, blockIdx.x);
    else                input_body(sm, x, win, bin, blockIdx.x - 8);
}

// ---------------------------------------------------------------------------
// k_sweep: smem layout (floats)
//   zin 0..4095 | zls 4096..36863 | qs 36864..38911 | wb 38912..55295 (2x8192)
//   bb 55296..56319 | lg 56320..56479 | mbar @56480 (2 x u64)
// ---------------------------------------------------------------------------
#define SW_FLOATS 56484
#define SW_BYTES  (SW_FLOATS * 4)

__device__ __forceinline__ void prefetch_chunk(int c, uint32_t wbB, uint32_t mbar0,
                                               const float* __restrict__ wblocks)
{
    if (c >= NCHUNKS) return;
    const uint32_t dst = wbB + (uint32_t)(c & 1) * 32768u;
    const uint32_t mb  = mbar0 + (uint32_t)(c & 1) * 8u;
    mbar_expect(mb, 32768u);
    if (c >= NCHUNKS - 2) {
        bulk_g2s(dst, g_WT + (c - (NCHUNKS - 2)) * 8192, 32768u, mb);
    } else {
        const int step = c / 6;
        const int l = step & 7;
        const int r = c - step * 6;
        if (r < 4) {
            bulk_g2s(dst,          g_Mt + l * 16384 + r * 4096, 16384u, mb);
            bulk_g2s(dst + 16384u, g_Nt + l * 16384 + r * 4096, 16384u, mb);
        } else {
            bulk_g2s(dst, wblocks + l * 16384 + (r - 4) * 8192, 32768u, mb);
        }
    }
}

__global__ __launch_bounds__(128, 1) void k_sweep(const float* __restrict__ wblocks,
                                                  const float* __restrict__ bblocks,
                                                  const float* __restrict__ wout,
                                                  const float* __restrict__ bout,
                                                  float* __restrict__ out)
{
    extern __shared__ float sm[];
    float* zin = sm;
    float* zls = sm + 4096;
    float* qs  = sm + 36864;
    float* wb  = sm + 38912;
    float* bb  = sm + 55296;
    float* lg  = sm + 56320;

    const uint32_t smem0 = s2u(sm);
    const uint32_t mbar0 = smem0 + 56480u * 4u;
    const uint32_t wbB   = smem0 + 38912u * 4u;

    const int tid  = threadIdx.x;
    const int wid  = tid >> 5;
    const int lane = tid & 31;
    const int r0   = wid * 4;       // warp's first row (of 16)
    const int row0 = blockIdx.x * 16;

    for (int idx = tid; idx < 4096; idx += 128) zin[idx] = g_zin[row0 * 256 + idx];
    for (int idx = tid; idx < 1024; idx += 128) bb[idx] = bblocks[idx];
    if (tid == 0) {
        mbar_init(mbar0, 1);
        mbar_init(mbar0 + 8, 1);
        asm volatile("fence.mbarrier_init.release.cluster;" ::: "memory");
    }
    __syncthreads();
    for (int idx = tid; idx < 32768; idx += 128) zls[idx] = zin[idx & 4095];
    if (tid == 0) { prefetch_chunk(0, wbB, mbar0, wblocks); prefetch_chunk(1, wbB, mbar0, wblocks); }
    __syncthreads();

    int c = 0;
    for (int it = 0; it < NSTEPS; it++) {
        for (int l = 0; l < NLAYERS; l++) {
            const float* carry = l ? (zls + (l - 1) * 4096) : zin;
            float* zl = zls + l * 4096;

            // stage q (warp-/lane-local)
#pragma unroll
            for (int rr = 0; rr < 4; rr++) {
                const int r = r0 + rr;
                float4 zu = ld4(&zl[r * 256 + lane * 4]);
                float4 cv = ld4(&carry[r * 256 + 128 + lane * 4]);
                float4 q;
                q.x = TANHK * tanhf(zu.x) + cv.x;
                q.y = TANHK * tanhf(zu.y) + cv.y;
                q.z = TANHK * tanhf(zu.z) + cv.z;
                q.w = TANHK * tanhf(zu.w) + cv.w;
                st4(&qs[r * 128 + lane * 4], q);
            }
            __syncwarp();

            // ---- u = M p - N q ----
            float4 acc[4];
#pragma unroll
            for (int r = 0; r < 4; r++) acc[r] = make_float4(0.f, 0.f, 0.f, 0.f);
            for (int kc = 0; kc < 4; kc++) {
                mbar_wait(mbar0 + (uint32_t)(c & 1) * 8u, (c >> 1) & 1);
                const float* Mt = wb + (c & 1) * 8192;
                const float* Nt = Mt + 4096;
#pragma unroll
                for (int kk4 = 0; kk4 < 8; kk4++) {
                    const int k0 = kc * 32 + kk4 * 4;
                    const int kl = kk4 * 4;
                    const float4 b4 = ld4(&bb[l * 128 + k0]);
                    float4 cu[4], qq[4];
#pragma unroll
                    for (int rr = 0; rr < 4; rr++) {
                        cu[rr] = ld4(&carry[(r0 + rr) * 256 + k0]);
                        qq[rr] = ld4(&qs[(r0 + rr) * 128 + k0]);
                    }
                    float p[4][4];
#pragma unroll
                    for (int rr = 0; rr < 4; rr++) {
#pragma unroll
                        for (int t = 0; t < 4; t++)
                            p[rr][t] = fmaf(DT_A, FC(b4, t), FC(cu[rr], t));
                    }
#pragma unroll
                    for (int t = 0; t < 4; t++) {
                        const float4 m = ld4(&Mt[(kl + t) * 128 + lane * 4]);
                        const float4 n = ld4(&Nt[(kl + t) * 128 + lane * 4]);
#pragma unroll
                        for (int rr = 0; rr < 4; rr++) {
                            const float pv = p[rr][t];
                            const float qv = FC(qq[rr], t);
                            acc[rr].x += pv * m.x - qv * n.x;
                            acc[rr].y += pv * m.y - qv * n.y;
                            acc[rr].z += pv * m.z - qv * n.z;
                            acc[rr].w += pv * m.w - qv * n.w;
                        }
                    }
                }
                __syncthreads();
                if (tid == 0) prefetch_chunk(c + 2, wbB, mbar0, wblocks);
                c++;
            }
#pragma unroll
            for (int rr = 0; rr < 4; rr++)
                st4(&zl[(r0 + rr) * 256 + lane * 4], acc[rr]);
            __syncwarp();

            // ---- v = (q + a * u W)/c ----
            float4 vac[4];
#pragma unroll
            for (int r = 0; r < 4; r++) vac[r] = make_float4(0.f, 0.f, 0.f, 0.f);
            for (int jc = 0; jc < 2; jc++) {
                mbar_wait(mbar0 + (uint32_t)(c & 1) * 8u, (c >> 1) & 1);
                const float* Ws = wb + (c & 1) * 8192;
#pragma unroll
                for (int jj4 = 0; jj4 < 16; jj4++) {
                    const int j0 = jc * 64 + jj4 * 4;
                    const int jl = jj4 * 4;
                    float4 u4[4];
#pragma unroll
                    for (int rr = 0; rr < 4; rr++)
                        u4[rr] = ld4(&zl[(r0 + rr) * 256 + j0]);
#pragma unroll
                    for (int t = 0; t < 4; t++) {
                        const float4 w = ld4(&Ws[(jl + t) * 128 + lane * 4]);
#pragma unroll
                        for (int rr = 0; rr < 4; rr++) {
                            const float uv = FC(u4[rr], t);
                            vac[rr].x += uv * w.x; vac[rr].y += uv * w.y;
                            vac[rr].z += uv * w.z; vac[rr].w += uv * w.w;
                        }
                    }
                }
                __syncthreads();
                if (tid == 0) prefetch_chunk(c + 2, wbB, mbar0, wblocks);
                c++;
            }
#pragma unroll
            for (int rr = 0; rr < 4; rr++) {
                const float4 q4 = ld4(&qs[(r0 + rr) * 128 + lane * 4]);
                float4 v;
                v.x = (q4.x + DT_A * vac[rr].x) * INVC;
                v.y = (q4.y + DT_A * vac[rr].y) * INVC;
                v.z = (q4.z + DT_A * vac[rr].z) * INVC;
                v.w = (q4.w + DT_A * vac[rr].w) * INVC;
                st4(&zl[(r0 + rr) * 256 + 128 + lane * 4], v);
            }
            __syncwarp();
        }
    }

    // ---- final block: u_out = z_in_u + a*b7 - a*(v7 @ W7^T) ----
    {
        float4 uac[4];
#pragma unroll
        for (int r = 0; r < 4; r++) uac[r] = make_float4(0.f, 0.f, 0.f, 0.f);
        const float* zl7 = zls + 7 * 4096;
        for (int ic = 0; ic < 2; ic++) {
            mbar_wait(mbar0 + (uint32_t)(c & 1) * 8u, (c >> 1) & 1);
            const float* Ws = wb + (c & 1) * 8192;   // WT rows ic*64..
#pragma unroll
            for (int ii4 = 0; ii4 < 16; ii4++) {
                const int i0 = ic * 64 + ii4 * 4;
                const int il = ii4 * 4;
                float4 v4[4];
#pragma unroll
                for (int rr = 0; rr < 4; rr++)
                    v4[rr] = ld4(&zl7[(r0 + rr) * 256 + 128 + i0]);
#pragma unroll
                for (int t = 0; t < 4; t++) {
                    const float4 w = ld4(&Ws[(il + t) * 128 + lane * 4]);
#pragma unroll
                    for (int rr = 0; rr < 4; rr++) {
                        const float vv = FC(v4[rr], t);
                        uac[rr].x += vv * w.x; uac[rr].y += vv * w.y;
                        uac[rr].z += vv * w.z; uac[rr].w += vv * w.w;
                    }
                }
            }
            __syncthreads();
            c++;
        }
#pragma unroll
        for (int rr = 0; rr < 4; rr++) {
            const float4 z4 = ld4(&zin[(r0 + rr) * 256 + lane * 4]);
            const float4 b4 = ld4(&bb[7 * 128 + lane * 4]);
            float4 uo;
            uo.x = z4.x + DT_A * b4.x - DT_A * uac[rr].x;
            uo.y = z4.y + DT_A * b4.y - DT_A * uac[rr].y;
            uo.z = z4.z + DT_A * b4.z - DT_A * uac[rr].z;
            uo.w = z4.w + DT_A * b4.w - DT_A * uac[rr].w;
            st4(&qs[(r0 + rr) * 128 + lane * 4], uo);
        }
    }
    __syncthreads();

    // ---- logits + softmax ----
    for (int t = tid; t < 160; t += 128) {
        const int r = t / 10, o = t % 10;
        const float* ur = qs + r * 128;
        const float* wr = wout + o * 128;
        float a = bout[o];
#pragma unroll 4
        for (int k = 0; k < U; k++) a += ur[k] * wr[k];
        lg[t] = a;
    }
    __syncthreads();
    if (tid < 16) {
        float mx = -1e30f;
#pragma unroll
        for (int o = 0; o < 10; o++) mx = fmaxf(mx, lg[tid * 10 + o]);
        float e[10], s = 0.f;
#pragma unroll
        for (int o = 0; o < 10; o++) { e[o] = expf(lg[tid * 10 + o] - mx); s += e[o]; }
        const float inv = 1.0f / s;
#pragma unroll
        for (int o = 0; o < 10; o++) out[(row0 + tid) * 10 + o] = e[o] * inv;
    }
}

// ---------------------------------------------------------------------------
extern "C" void kernel_launch(void* const* d_in, const int* in_sizes, int n_in,
                              void* d_out, int out_size)
{
    const float* x     = (const float*)d_in[0];
    const float* w_in  = (const float*)d_in[1];
    const float* b_in  = (const float*)d_in[2];
    const float* w_blk = (const float*)d_in[3];
    const float* b_blk = (const float*)d_in[4];
    const float* w_out = (const float*)d_in[5];
    const float* b_out = (const float*)d_in[6];
    float* out = (float*)d_out;

    cudaFuncSetAttribute(k_pre,   cudaFuncAttributeMaxDynamicSharedMemorySize, PREP_SMEM);
    cudaFuncSetAttribute(k_sweep, cudaFuncAttributeMaxDynamicSharedMemorySize, SW_BYTES);

    k_pre  <<<136, 256, PREP_SMEM>>>(x, w_in, b_in, w_blk);
    k_sweep<<<128, 128, SW_BYTES>>>(w_blk, b_blk, w_out, b_out, out);
}

// round 4
// speedup vs baseline: 1.3378x; 1.1103x over previous
#include <cuda_runtime.h>
#include <cstdint>
#include <math.h>

// ---------------------------------------------------------------------------
// TransNetSweeping on GB300 — fused fp32, async weights, 8-warp CTAs (R3).
//
// Math: A_l = [[I, aW],[-aW^T, cI]], a=0.1, c=11.
//   S = I + (a^2/c) W W^T,  M = S^{-1},  N = (a/c) M W
//   u = M p - N q ;  v = (q + a W^T u)/c
//   p = a*b_l + carry_u ; q = 10*tanh(z_l_u) + carry_v
// Fixed 15 Gauss-Seidel sweeps.
//
// k_sweep: 128 CTAs x 256 thr (8 warps = 2/SMSP for latency hiding).
// Warp = (row-group of 4) x (column half of 64). Weights stream via
// cp.async.bulk double buffer (2x32KB), flat 722-chunk sequence.
// ---------------------------------------------------------------------------

#define BATCH    2048
#define U        128
#define NLAYERS  8
#define NSTEPS   15

#define DT_A     0.1f
#define INVC     (1.0f/11.0f)
#define TANHK    10.0f

#define NCHUNKS  (NSTEPS * NLAYERS * 6 + 2)   // 722

__device__ float g_zin[BATCH * 256];
__device__ float g_Mt [NLAYERS * U * U];      // Mt[l][k][j] = M[j][k]
__device__ float g_Nt [NLAYERS * U * U];      // Nt[l][k][j] = N[j][k]
__device__ float g_WT [U * U];                // WT[i][k] = W7[k][i]

__device__ __forceinline__ float4 ld4(const float* p) { return *(const float4*)p; }
__device__ __forceinline__ float2 ld2(const float* p) { return *(const float2*)p; }
__device__ __forceinline__ void   st4(float* p, float4 v) { *(float4*)p = v; }
__device__ __forceinline__ void   st2(float* p, float2 v) { *(float2*)p = v; }
#define FC(v,t) (((const float*)&(v))[t])

__device__ __forceinline__ uint32_t s2u(const void* p) {
    uint32_t a;
    asm("{ .reg .u64 t; cvta.to.shared.u64 t, %1; cvt.u32.u64 %0, t; }" : "=r"(a) : "l"(p));
    return a;
}
__device__ __forceinline__ void mbar_init(uint32_t m, uint32_t cnt) {
    asm volatile("mbarrier.init.shared.b64 [%0], %1;" :: "r"(m), "r"(cnt) : "memory");
}
__device__ __forceinline__ void mbar_expect(uint32_t m, uint32_t tx) {
    asm volatile("mbarrier.arrive.expect_tx.shared.b64 _, [%0], %1;" :: "r"(m), "r"(tx) : "memory");
}
__device__ __forceinline__ void bulk_g2s(uint32_t dst, const void* src, uint32_t bytes, uint32_t m) {
    asm volatile("cp.async.bulk.shared::cluster.global.mbarrier::complete_tx::bytes [%0], [%1], %2, [%3];"
                 :: "r"(dst), "l"(src), "r"(bytes), "r"(m) : "memory");
}
__device__ __forceinline__ void mbar_wait(uint32_t m, uint32_t phase) {
    uint32_t done;
    do {
        asm volatile("{\n\t.reg .pred p;\n\t"
                     "mbarrier.try_wait.parity.acquire.cta.shared::cta.b64 p, [%1], %2, 0x989680;\n\t"
                     "selp.b32 %0, 1, 0, p;\n\t}"
                     : "=r"(done) : "r"(m), "r"(phase) : "memory");
    } while (!done);
}

// ---------------------------------------------------------------------------
// k_pre: merged prep (CTAs 0..7) + input projection (CTAs 8..135). Block 256.
// ---------------------------------------------------------------------------
#define WS_S 129
#define AS_S 260
#define PREP_SMEM ((128*WS_S + 128*AS_S + 128) * 4)

__device__ void prep_body(float* sm, const float* __restrict__ wblocks, int l)
{
    float* Wsh  = sm;
    float* aug  = sm + 128 * WS_S;
    float* colb = aug + 128 * AS_S;
    const int tid = threadIdx.x;
    const float* Wg = wblocks + l * U * U;

    for (int idx = tid; idx < U * U; idx += 256)
        Wsh[(idx >> 7) * WS_S + (idx & 127)] = Wg[idx];
    __syncthreads();

    const float kscl = (DT_A * DT_A) * INVC;
#pragma unroll 1
    for (int rep = 0; rep < 2; rep++) {
        const int pos = tid + rep * 256;
        const int ti = pos >> 4, tj = pos & 15;
        float acc[4][8];
#pragma unroll
        for (int r = 0; r < 4; r++)
#pragma unroll
            for (int j = 0; j < 8; j++) acc[r][j] = 0.f;
        for (int k = 0; k < U; k++) {
            float wi[4], wj[8];
#pragma unroll
            for (int r = 0; r < 4; r++) wi[r] = Wsh[(ti*4 + r) * WS_S + k];
#pragma unroll
            for (int j = 0; j < 8; j++) wj[j] = Wsh[(tj*8 + j) * WS_S + k];
#pragma unroll
            for (int r = 0; r < 4; r++)
#pragma unroll
                for (int j = 0; j < 8; j++) acc[r][j] += wi[r] * wj[j];
        }
#pragma unroll
        for (int r = 0; r < 4; r++)
#pragma unroll
            for (int j = 0; j < 8; j++) {
                int i = ti*4 + r, jj = tj*8 + j;
                aug[i * AS_S + jj] = kscl * acc[r][j] + (i == jj ? 1.f : 0.f);
            }
    }
    for (int idx = tid; idx < U * U; idx += 256) {
        int i = idx >> 7, j = idx & 127;
        aug[i * AS_S + 128 + j] = (i == j) ? 1.f : 0.f;
    }

    const int f4c = tid & 63, rgp = tid >> 6;
    for (int p = 0; p < U; p++) {
        __syncthreads();
        const float inv = 1.0f / aug[p * AS_S + p];
        if (tid < 128 && tid != p) colb[tid] = aug[tid * AS_S + p];
        __syncthreads();
        aug[p * AS_S + tid] *= inv;
        __syncthreads();
        const float4 rp = ld4(&aug[p * AS_S + f4c * 4]);
        for (int i = rgp * 32; i < rgp * 32 + 32; i++) {
            if (i == p) continue;
            const float fac = colb[i];
            float4 a = ld4(&aug[i * AS_S + f4c * 4]);
            a.x -= fac * rp.x; a.y -= fac * rp.y;
            a.z -= fac * rp.z; a.w -= fac * rp.w;
            st4(&aug[i * AS_S + f4c * 4], a);
        }
    }
    __syncthreads();

    // aug_left[m][j] := M[j][m]
    for (int idx = tid; idx < U * U; idx += 256) {
        int m = idx >> 7, j = idx & 127;
        aug[m * AS_S + j] = aug[j * AS_S + 128 + m];
    }
    __syncthreads();

    for (int idx = tid; idx < U * U; idx += 256) {
        int k = idx >> 7, j = idx & 127;
        g_Mt[l * U * U + idx] = aug[k * AS_S + j];
    }

    const float ac = DT_A * INVC;
#pragma unroll 1
    for (int rep = 0; rep < 2; rep++) {
        const int pos = tid + rep * 256;
        const int tk = pos >> 4, tj = pos & 15;
        float acc[4][8];
#pragma unroll
        for (int r = 0; r < 4; r++)
#pragma unroll
            for (int j = 0; j < 8; j++) acc[r][j] = 0.f;
        for (int m = 0; m < U; m++) {
            float wv[4], mv[8];
#pragma unroll
            for (int r = 0; r < 4; r++) wv[r] = Wsh[m * WS_S + tk*4 + r];
#pragma unroll
            for (int j = 0; j < 8; j++) mv[j] = aug[m * AS_S + tj*8 + j];
#pragma unroll
            for (int r = 0; r < 4; r++)
#pragma unroll
                for (int j = 0; j < 8; j++) acc[r][j] += wv[r] * mv[j];
        }
#pragma unroll
        for (int r = 0; r < 4; r++)
#pragma unroll
            for (int j = 0; j < 8; j++)
                g_Nt[l * U * U + (tk*4 + r) * U + tj*8 + j] = ac * acc[r][j];
    }

    if (l == NLAYERS - 1) {
        for (int idx = tid; idx < U * U; idx += 256) {
            int i = idx >> 7, j = idx & 127;
            g_WT[i * U + j] = Wsh[j * WS_S + i];
        }
    }
}

__device__ void input_body(float* sm, const float* __restrict__ x,
                           const float* __restrict__ win,
                           const float* __restrict__ bin, int bid)
{
    float* ws = sm;            // [16][132]
    float* xs = sm + 16 * 132; // [16][20]
    const int tid = threadIdx.x;
    const int row0 = bid * 16;
    const int rg = tid >> 5, cg = tid & 31;

    float4 acc[4];
#pragma unroll
    for (int r = 0; r < 4; r++) acc[r] = make_float4(0.f, 0.f, 0.f, 0.f);

    for (int kc = 0; kc < 49; kc++) {
        const int k0 = kc * 16;
        __syncthreads();
        {   // ws[kk][n] = win[n][k0+kk]; 256 threads, 8 values each
            const int n = tid & 127, h = tid >> 7;
            const float* wr = win + n * 784 + k0 + h * 8;
            float4 a = ld4(wr), b = ld4(wr + 4);
            ws[(h*8+0)*132 + n] = a.x; ws[(h*8+1)*132 + n] = a.y;
            ws[(h*8+2)*132 + n] = a.z; ws[(h*8+3)*132 + n] = a.w;
            ws[(h*8+4)*132 + n] = b.x; ws[(h*8+5)*132 + n] = b.y;
            ws[(h*8+6)*132 + n] = b.z; ws[(h*8+7)*132 + n] = b.w;
        }
        {
            const int r = tid >> 4, kk = tid & 15;
            xs[kk * 20 + r] = x[(row0 + r) * 784 + k0 + kk];
        }
        __syncthreads();
        if (tid < 128) {
#pragma unroll
            for (int kk = 0; kk < 16; kk++) {
                float4 wv = ld4(&ws[kk * 132 + cg * 4]);
#pragma unroll
                for (int rr = 0; rr < 4; rr++) {
                    float xv = xs[kk * 20 + rg * 4 + rr];
                    acc[rr].x += xv * wv.x; acc[rr].y += xv * wv.y;
                    acc[rr].z += xv * wv.z; acc[rr].w += xv * wv.w;
                }
            }
        }
    }

    if (tid < 128) {
        const float4 b4 = ld4(bin + cg * 4);
#pragma unroll
        for (int rr = 0; rr < 4; rr++) {
            const int row = row0 + rg * 4 + rr;
            float4 v;
            v.x = acc[rr].x + b4.x; v.y = acc[rr].y + b4.y;
            v.z = acc[rr].z + b4.z; v.w = acc[rr].w + b4.w;
            st4(&g_zin[row * 256 + cg * 4], v);
            float4 t;
            t.x = tanhf(v.x); t.y = tanhf(v.y); t.z = tanhf(v.z); t.w = tanhf(v.w);
            st4(&g_zin[row * 256 + 128 + cg * 4], t);
        }
    }
}

__global__ __launch_bounds__(256) void k_pre(const float* __restrict__ x,
                                             const float* __restrict__ win,
                                             const float* __restrict__ bin,
                                             const float* __restrict__ wblocks)
{
    extern __shared__ float sm[];
    if (blockIdx.x < 8) prep_body(sm, wblocks, blockIdx.x);
    else                input_body(sm, x, win, bin, blockIdx.x - 8);
}

// ---------------------------------------------------------------------------
// k_sweep smem layout (floats):
//   zin 0..4095 | zls 4096..36863 | qs 36864..38911 | wb 38912..55295 (2x8192)
//   bb 55296..56319 | lg 56320..56479 | mbar @56480 (2 x u64)
// ---------------------------------------------------------------------------
#define SW_FLOATS 56484
#define SW_BYTES  (SW_FLOATS * 4)

__device__ __forceinline__ void prefetch_chunk(int c, uint32_t wbB, uint32_t mbar0,
                                               const float* __restrict__ wblocks)
{
    if (c >= NCHUNKS) return;
    const uint32_t dst = wbB + (uint32_t)(c & 1) * 32768u;
    const uint32_t mb  = mbar0 + (uint32_t)(c & 1) * 8u;
    mbar_expect(mb, 32768u);
    if (c >= NCHUNKS - 2) {
        bulk_g2s(dst, g_WT + (c - (NCHUNKS - 2)) * 8192, 32768u, mb);
    } else {
        const int step = c / 6;
        const int l = step & 7;
        const int r = c - step * 6;
        if (r < 4) {
            bulk_g2s(dst,          g_Mt + l * 16384 + r * 4096, 16384u, mb);
            bulk_g2s(dst + 16384u, g_Nt + l * 16384 + r * 4096, 16384u, mb);
        } else {
            bulk_g2s(dst, wblocks + l * 16384 + (r - 4) * 8192, 32768u, mb);
        }
    }
}

__global__ __launch_bounds__(256, 1) void k_sweep(const float* __restrict__ wblocks,
                                                  const float* __restrict__ bblocks,
                                                  const float* __restrict__ wout,
                                                  const float* __restrict__ bout,
                                                  float* __restrict__ out)
{
    extern __shared__ float sm[];
    float* zin = sm;
    float* zls = sm + 4096;
    float* qs  = sm + 36864;
    float* wb  = sm + 38912;
    float* bb  = sm + 55296;
    float* lg  = sm + 56320;

    const uint32_t smem0 = s2u(sm);
    const uint32_t mbar0 = smem0 + 56480u * 4u;
    const uint32_t wbB   = smem0 + 38912u * 4u;

    const int tid   = threadIdx.x;
    const int wid   = tid >> 5;
    const int lane  = tid & 31;
    const int rgrp  = wid & 3;        // row group
    const int chalf = wid >> 2;       // column half
    const int r0    = rgrp * 4;
    const int c0    = chalf * 64;
    const int cl    = c0 + lane * 2;  // this lane's first column (of 128)
    const int row0  = blockIdx.x * 16;

    for (int idx = tid; idx < 4096; idx += 256) zin[idx] = g_zin[row0 * 256 + idx];
    for (int idx = tid; idx < 1024; idx += 256) bb[idx] = bblocks[idx];
    if (tid == 0) {
        mbar_init(mbar0, 1);
        mbar_init(mbar0 + 8, 1);
        asm volatile("fence.mbarrier_init.release.cluster;" ::: "memory");
    }
    __syncthreads();
    for (int idx = tid; idx < 32768; idx += 256) zls[idx] = zin[idx & 4095];
    if (tid == 0) { prefetch_chunk(0, wbB, mbar0, wblocks); prefetch_chunk(1, wbB, mbar0, wblocks); }
    __syncthreads();

    int c = 0;
    for (int it = 0; it < NSTEPS; it++) {
        for (int l = 0; l < NLAYERS; l++) {
            const float* carry = l ? (zls + (l - 1) * 4096) : zin;
            float* zl = zls + l * 4096;

            // stage q: warp covers its 4 rows x its 64-col k-half
#pragma unroll
            for (int rr = 0; rr < 4; rr++) {
                const int r = r0 + rr;
                float2 zu = ld2(&zl[r * 256 + cl]);
                float2 cv = ld2(&carry[r * 256 + 128 + cl]);
                float2 q;
                q.x = TANHK * tanhf(zu.x) + cv.x;
                q.y = TANHK * tanhf(zu.y) + cv.y;
                st2(&qs[r * 128 + cl], q);
            }
            __syncthreads();   // qs visible to all warps (broadcast over k)

            // ---- u = M p - N q ----
            float2 acc[4];
#pragma unroll
            for (int r = 0; r < 4; r++) acc[r] = make_float2(0.f, 0.f);
            for (int kc = 0; kc < 4; kc++) {
                mbar_wait(mbar0 + (uint32_t)(c & 1) * 8u, (c >> 1) & 1);
                const float* Mt = wb + (c & 1) * 8192;
                const float* Nt = Mt + 4096;
#pragma unroll
                for (int kk4 = 0; kk4 < 8; kk4++) {
                    const int k0 = kc * 32 + kk4 * 4;
                    const int kl = kk4 * 4;
                    const float4 b4 = ld4(&bb[l * 128 + k0]);
                    float4 cu[4], qq[4];
#pragma unroll
                    for (int rr = 0; rr < 4; rr++) {
                        cu[rr] = ld4(&carry[(r0 + rr) * 256 + k0]);
                        qq[rr] = ld4(&qs[(r0 + rr) * 128 + k0]);
                    }
                    float p[4][4];
#pragma unroll
                    for (int rr = 0; rr < 4; rr++)
#pragma unroll
                        for (int t = 0; t < 4; t++)
                            p[rr][t] = fmaf(DT_A, FC(b4, t), FC(cu[rr], t));
#pragma unroll
                    for (int t = 0; t < 4; t++) {
                        const float2 m = ld2(&Mt[(kl + t) * 128 + cl]);
                        const float2 n = ld2(&Nt[(kl + t) * 128 + cl]);
#pragma unroll
                        for (int rr = 0; rr < 4; rr++) {
                            const float pv = p[rr][t];
                            const float qv = FC(qq[rr], t);
                            acc[rr].x += pv * m.x - qv * n.x;
                            acc[rr].y += pv * m.y - qv * n.y;
                        }
                    }
                }
                if (kc == 3) {   // store u before the slot-reuse barrier
#pragma unroll
                    for (int rr = 0; rr < 4; rr++)
                        st2(&zl[(r0 + rr) * 256 + cl], acc[rr]);
                }
                __syncthreads();
                if (tid == 0) prefetch_chunk(c + 2, wbB, mbar0, wblocks);
                c++;
            }

            // ---- v = (q + a * u W)/c ----
            float2 vac[4];
#pragma unroll
            for (int r = 0; r < 4; r++) vac[r] = make_float2(0.f, 0.f);
            for (int jc = 0; jc < 2; jc++) {
                mbar_wait(mbar0 + (uint32_t)(c & 1) * 8u, (c >> 1) & 1);
                const float* Ws = wb + (c & 1) * 8192;
#pragma unroll
                for (int jj4 = 0; jj4 < 16; jj4++) {
                    const int j0 = jc * 64 + jj4 * 4;
                    const int jl = jj4 * 4;
                    float4 u4[4];
#pragma unroll
                    for (int rr = 0; rr < 4; rr++)
                        u4[rr] = ld4(&zl[(r0 + rr) * 256 + j0]);
#pragma unroll
                    for (int t = 0; t < 4; t++) {
                        const float2 w = ld2(&Ws[(jl + t) * 128 + cl]);
#pragma unroll
                        for (int rr = 0; rr < 4; rr++) {
                            const float uv = FC(u4[rr], t);
                            vac[rr].x += uv * w.x;
                            vac[rr].y += uv * w.y;
                        }
                    }
                }
                if (jc == 1) {   // epilogue + store v before the barrier
#pragma unroll
                    for (int rr = 0; rr < 4; rr++) {
                        const float2 q2 = ld2(&qs[(r0 + rr) * 128 + cl]);
                        float2 v;
                        v.x = (q2.x + DT_A * vac[rr].x) * INVC;
                        v.y = (q2.y + DT_A * vac[rr].y) * INVC;
                        st2(&zl[(r0 + rr) * 256 + 128 + cl], v);
                    }
                }
                __syncthreads();
                if (tid == 0) prefetch_chunk(c + 2, wbB, mbar0, wblocks);
                c++;
            }
        }
    }

    // ---- final block: u_out = z_in_u + a*b7 - a*(v7 @ W7^T) -> qs ----
    {
        float2 uac[4];
#pragma unroll
        for (int r = 0; r < 4; r++) uac[r] = make_float2(0.f, 0.f);
        const float* zl7 = zls + 7 * 4096;
        for (int ic = 0; ic < 2; ic++) {
            mbar_wait(mbar0 + (uint32_t)(c & 1) * 8u, (c >> 1) & 1);
            const float* Ws = wb + (c & 1) * 8192;   // WT rows ic*64..
#pragma unroll
            for (int ii4 = 0; ii4 < 16; ii4++) {
                const int i0 = ic * 64 + ii4 * 4;
                const int il = ii4 * 4;
                float4 v4[4];
#pragma unroll
                for (int rr = 0; rr < 4; rr++)
                    v4[rr] = ld4(&zl7[(r0 + rr) * 256 + 128 + i0]);
#pragma unroll
                for (int t = 0; t < 4; t++) {
                    const float2 w = ld2(&Ws[(il + t) * 128 + cl]);
#pragma unroll
                    for (int rr = 0; rr < 4; rr++) {
                        const float vv = FC(v4[rr], t);
                        uac[rr].x += vv * w.x;
                        uac[rr].y += vv * w.y;
                    }
                }
            }
            if (ic == 1) {
#pragma unroll
                for (int rr = 0; rr < 4; rr++) {
                    const float2 z2 = ld2(&zin[(r0 + rr) * 256 + cl]);
                    const float2 b2 = ld2(&bb[7 * 128 + cl]);
                    float2 uo;
                    uo.x = z2.x + DT_A * b2.x - DT_A * uac[rr].x;
                    uo.y = z2.y + DT_A * b2.y - DT_A * uac[rr].y;
                    st2(&qs[(r0 + rr) * 128 + cl], uo);
                }
            }
            __syncthreads();
            c++;
        }
    }

    // ---- logits + softmax ----
    for (int t = tid; t < 160; t += 256) {
        const int r = t / 10, o = t % 10;
        const float* ur = qs + r * 128;
        const float* wr = wout + o * 128;
        float a = bout[o];
#pragma unroll 4
        for (int k = 0; k < U; k++) a += ur[k] * wr[k];
        lg[t] = a;
    }
    __syncthreads();
    if (tid < 16) {
        float mx = -1e30f;
#pragma unroll
        for (int o = 0; o < 10; o++) mx = fmaxf(mx, lg[tid * 10 + o]);
        float e[10], s = 0.f;
#pragma unroll
        for (int o = 0; o < 10; o++) { e[o] = expf(lg[tid * 10 + o] - mx); s += e[o]; }
        const float inv = 1.0f / s;
#pragma unroll
        for (int o = 0; o < 10; o++) out[(row0 + tid) * 10 + o] = e[o] * inv;
    }
}

// ---------------------------------------------------------------------------
extern "C" void kernel_launch(void* const* d_in, const int* in_sizes, int n_in,
                              void* d_out, int out_size)
{
    const float* x     = (const float*)d_in[0];
    const float* w_in  = (const float*)d_in[1];
    const float* b_in  = (const float*)d_in[2];
    const float* w_blk = (const float*)d_in[3];
    const float* b_blk = (const float*)d_in[4];
    const float* w_out = (const float*)d_in[5];
    const float* b_out = (const float*)d_in[6];
    float* out = (float*)d_out;

    cudaFuncSetAttribute(k_pre,   cudaFuncAttributeMaxDynamicSharedMemorySize, PREP_SMEM);
    cudaFuncSetAttribute(k_sweep, cudaFuncAttributeMaxDynamicSharedMemorySize, SW_BYTES);

    k_pre  <<<136, 256, PREP_SMEM>>>(x, w_in, b_in, w_blk);
    k_sweep<<<128, 256, SW_BYTES>>>(w_blk, b_blk, w_out, b_out, out);
}